// round 5
// baseline (speedup 1.0000x reference)
#include <cuda_runtime.h>
#include <cuda_bf16.h>
#include <cstdint>

#define D        256
#define K        1024
#define HW       1024
#define NTOK     32768
#define NBLK     256
#define NBLK_G   512
#define IDX_OFF  8388608
#define LOSS_OFF 8421376
#define MARGIN   0.05f

// gemm smem layout (bytes). 64 tokens/block.
#define OFF_AH   0          // 64 x 264 halves = 33792
#define OFF_AL   33792
#define OFF_B    67584      // 2 bufs x 16896 (16 codes x 528 x 2 halves)
#define BBUF_SZ  16896
#define BHALF_SZ 8448
#define OFF_CN   101376     // 4096
#define OFF_STG  105472     // 64*2*16 = 2048
#define SMEM_SZ  107520

__device__ float    g_cnorm[K];
__device__ float    g_partial[NBLK];
__device__ int      g_idx[NTOK];
__device__ int4     g_doubt[NTOK];
__device__ int      g_doubt_cnt;
__device__ uint16_t g_cbh[K * D];
__device__ uint16_t g_cbl[K * D];

// ---------------- helpers ----------------
__device__ __forceinline__ uint32_t smem_u32(const void* p) {
    uint32_t a;
    asm("{ .reg .u64 t; cvta.to.shared.u64 t, %1; cvt.u32.u64 %0, t; }" : "=r"(a) : "l"(p));
    return a;
}
#define CP_ASYNC16(dst, src) \
    asm volatile("cp.async.cg.shared.global [%0], [%1], 16;" :: "r"(dst), "l"(src) : "memory")
#define CP_COMMIT() asm volatile("cp.async.commit_group;" ::: "memory")
#define CP_WAIT1()  asm volatile("cp.async.wait_group 1;" ::: "memory")
#define CP_WAIT0()  asm volatile("cp.async.wait_group 0;" ::: "memory")

__device__ __forceinline__ void ldsm_x4(uint32_t* r, uint32_t a) {
    asm volatile("ldmatrix.sync.aligned.m8n8.x4.shared.b16 {%0,%1,%2,%3}, [%4];"
        : "=r"(r[0]), "=r"(r[1]), "=r"(r[2]), "=r"(r[3]) : "r"(a));
}
__device__ __forceinline__ void ldsm_x2(uint32_t* r, uint32_t a) {
    asm volatile("ldmatrix.sync.aligned.m8n8.x2.shared.b16 {%0,%1}, [%2];"
        : "=r"(r[0]), "=r"(r[1]) : "r"(a));
}
__device__ __forceinline__ void mma_bf16(float* c, const uint32_t* a, const uint32_t* b) {
    asm volatile(
        "mma.sync.aligned.m16n8k16.row.col.f32.bf16.bf16.f32 "
        "{%0,%1,%2,%3}, {%4,%5,%6,%7}, {%8,%9}, {%0,%1,%2,%3};"
        : "+f"(c[0]), "+f"(c[1]), "+f"(c[2]), "+f"(c[3])
        : "r"(a[0]), "r"(a[1]), "r"(a[2]), "r"(a[3]), "r"(b[0]), "r"(b[1]));
}
__device__ __forceinline__ bool better(float v, int i, float V, int I) {
    return v < V || (v == V && i < I);
}

// ---------------- Kernel 0: split codebook to bf16 hi/lo ----------------
__global__ void prep_kernel(const float* __restrict__ cb) {
    int i = blockIdx.x * 256 + threadIdx.x;
    float v = cb[i];
    __nv_bfloat16 h = __float2bfloat16(v);
    g_cbh[i] = __bfloat16_as_ushort(h);
    g_cbl[i] = __bfloat16_as_ushort(__float2bfloat16(v - __bfloat162float(h)));
}

// ---------------- Kernel 1: cnorm + counter reset ----------------
__global__ void cnorm_kernel(const float* __restrict__ cb) {
    if (blockIdx.x == 0 && threadIdx.x == 0) g_doubt_cnt = 0;
    int k = blockIdx.x * 8 + (threadIdx.x >> 5);
    int lane = threadIdx.x & 31;
    const float* row = cb + k * D;
    float s = 0.f;
#pragma unroll
    for (int d = lane; d < D; d += 32) { float v = row[d]; s = fmaf(v, v, s); }
#pragma unroll
    for (int o = 16; o; o >>= 1) s += __shfl_xor_sync(~0u, s, o);
    if (lane == 0) g_cnorm[k] = s;
}

// ---------------- Kernel 2: HMMA bf16x3 GEMM + top-2 argmin ----------------
// 512 blocks x 64 tokens; 2 CTAs/SM. Warp tile 16 tok x 8 codes; chunks of 16 codes.
__global__ __launch_bounds__(256, 2) void vq_gemm(const float* __restrict__ z) {
    extern __shared__ char sm[];
    const uint32_t su = smem_u32(sm);
    const int t = threadIdx.x, w = t >> 5, lane = t & 31;
    const int g = lane >> 2, p = lane & 3;
    const int mw = w >> 1, nw = w & 1;
    const int n0 = blockIdx.x * 64;
    const int b = n0 >> 10, hw0 = n0 & 1023;
    const float* zb = z + b * (D * HW) + hw0;

    uint16_t* sAh = (uint16_t*)(sm + OFF_AH);
    uint16_t* sAl = (uint16_t*)(sm + OFF_AL);
    float*    scn = (float*)(sm + OFF_CN);
    float4*   stg = (float4*)(sm + OFF_STG);

    // ---- A: load z coalesced (64 tokens x 256 dims), split hi/lo into smem ----
#pragma unroll
    for (int j = 0; j < 16; j++) {
        int l = j * 256 + t;
        int d = l >> 4, f4 = l & 15;
        float4 v = *(const float4*)(zb + d * HW + f4 * 4);
        float vv[4] = {v.x, v.y, v.z, v.w};
#pragma unroll
        for (int q = 0; q < 4; q++) {
            int tok = f4 * 4 + q;
            __nv_bfloat16 h = __float2bfloat16(vv[q]);
            sAh[tok * 264 + d] = __bfloat16_as_ushort(h);
            sAl[tok * 264 + d] =
                __bfloat16_as_ushort(__float2bfloat16(vv[q] - __bfloat162float(h)));
        }
    }
    for (int c = t; c < K; c += 256) scn[c] = g_cnorm[c];

    // prefetch B chunk 0 (16 codes, hi+lo)
#pragma unroll
    for (int j = 0; j < 4; j++) {
        int s = j * 256 + t;
        int half = s >> 9, code = (s >> 5) & 15, seg = s & 31;
        uint32_t dst = su + OFF_B + half * BHALF_SZ + code * 528 + seg * 16;
        const char* src = (const char*)(half ? g_cbl : g_cbh) + code * 512 + seg * 16;
        CP_ASYNC16(dst, src);
    }
    CP_COMMIT();
    __syncthreads();

    // ldmatrix lane addresses
    const int l8 = lane & 7, mat = lane >> 3;
    const uint32_t aoff = (uint32_t)((mw * 16 + l8 + (mat & 1) * 8) * 528 + (mat >> 1) * 16);
    const uint32_t aAddrH = su + OFF_AH + aoff;
    const uint32_t aAddrL = su + OFF_AL + aoff;
    const uint32_t boff = (uint32_t)((nw * 8 + l8) * 528 + ((lane >> 3) & 1) * 16);

    float rv1[2] = {3.4e38f, 3.4e38f}, rv2[2] = {3.4e38f, 3.4e38f};
    int   ri1[2] = {0, 0},             ri2[2] = {0, 0};

    for (int nc = 0; nc < 64; nc++) {
        if (nc < 63) {
            int nn = nc + 1, buf = nn & 1;
#pragma unroll
            for (int j = 0; j < 4; j++) {
                int s = j * 256 + t;
                int half = s >> 9, code = (s >> 5) & 15, seg = s & 31;
                uint32_t dst = su + OFF_B + buf * BBUF_SZ + half * BHALF_SZ + code * 528 + seg * 16;
                const char* src = (const char*)(half ? g_cbl : g_cbh)
                                + (nn * 16 + code) * 512 + seg * 16;
                CP_ASYNC16(dst, src);
            }
            CP_COMMIT();
            CP_WAIT1();
        } else {
            CP_WAIT0();
        }
        __syncthreads();

        const uint32_t base = su + OFF_B + (uint32_t)(nc & 1) * BBUF_SZ;
        const uint32_t bH = base + boff;
        const uint32_t bL = base + BHALF_SZ + boff;

        float acc0[4] = {0.f, 0.f, 0.f, 0.f};
        float acc1[4] = {0.f, 0.f, 0.f, 0.f};
        float acc2[4] = {0.f, 0.f, 0.f, 0.f};

#pragma unroll
        for (int ks = 0; ks < 16; ks++) {
            uint32_t ah[4], al[4], bh[2], bl[2];
            ldsm_x4(ah, aAddrH + ks * 32);
            ldsm_x4(al, aAddrL + ks * 32);
            ldsm_x2(bh, bH + ks * 32);
            ldsm_x2(bl, bL + ks * 32);
            mma_bf16(acc0, ah, bh);
            mma_bf16(acc1, ah, bl);
            mma_bf16(acc2, al, bh);
        }

        // fold into running top-2 (codes ascending)
#pragma unroll
        for (int q = 0; q < 2; q++) {
            int c = nc * 16 + nw * 8 + 2 * p + q;
            float cn = scn[c];
#pragma unroll
            for (int rr = 0; rr < 2; rr++) {
                float dot = acc0[rr * 2 + q] + acc1[rr * 2 + q] + acc2[rr * 2 + q];
                float v = fmaf(-2.f, dot, cn);
                if (v < rv1[rr]) {
                    rv2[rr] = rv1[rr]; ri2[rr] = ri1[rr];
                    rv1[rr] = v;       ri1[rr] = c;
                } else if (v < rv2[rr]) {
                    rv2[rr] = v;       ri2[rr] = c;
                }
            }
        }
        __syncthreads();   // all reads done before buffer reuse
    }

    // ---- merge top-2 across p lanes ----
#pragma unroll
    for (int o = 1; o <= 2; o <<= 1) {
#pragma unroll
        for (int rr = 0; rr < 2; rr++) {
            float ov1 = __shfl_xor_sync(~0u, rv1[rr], o);
            int   oi1 = __shfl_xor_sync(~0u, ri1[rr], o);
            float ov2 = __shfl_xor_sync(~0u, rv2[rr], o);
            int   oi2 = __shfl_xor_sync(~0u, ri2[rr], o);
            if (better(ov1, oi1, rv1[rr], ri1[rr])) {
                if (better(rv1[rr], ri1[rr], ov2, oi2)) { rv2[rr] = rv1[rr]; ri2[rr] = ri1[rr]; }
                else                                    { rv2[rr] = ov2;     ri2[rr] = oi2; }
                rv1[rr] = ov1; ri1[rr] = oi1;
            } else if (better(ov1, oi1, rv2[rr], ri2[rr])) {
                rv2[rr] = ov1; ri2[rr] = oi1;
            }
        }
    }
    if (p == 0) {
#pragma unroll
        for (int rr = 0; rr < 2; rr++) {
            int tok = mw * 16 + rr * 8 + g;
            stg[tok * 2 + nw] = make_float4(rv1[rr], __int_as_float(ri1[rr]),
                                            rv2[rr], __int_as_float(ri2[rr]));
        }
    }
    __syncthreads();

    if (t < 64) {
        float4 a = stg[t * 2], bq = stg[t * 2 + 1];
        float v1 = a.x, v2 = a.z; int i1 = __float_as_int(a.y), i2 = __float_as_int(a.w);
        float w1 = bq.x, w2 = bq.z; int j1 = __float_as_int(bq.y), j2 = __float_as_int(bq.w);
        float fv1, fv2; int fi1, fi2;
        if (better(w1, j1, v1, i1)) {
            fv1 = w1; fi1 = j1;
            if (better(v1, i1, w2, j2)) { fv2 = v1; fi2 = i1; } else { fv2 = w2; fi2 = j2; }
        } else {
            fv1 = v1; fi1 = i1;
            if (better(w1, j1, v2, i2)) { fv2 = w1; fi2 = j1; } else { fv2 = v2; fi2 = i2; }
        }
        g_idx[n0 + t] = fi1;
        if (fv2 - fv1 < MARGIN) {
            int s = atomicAdd(&g_doubt_cnt, 1);
            g_doubt[s] = make_int4(n0 + t, fi1, fi2, 0);
        }
    }
}

// ---------------- Kernel 3: exact fp32 rescue ----------------
__global__ void rescue_kernel(const float* __restrict__ z, const float* __restrict__ cb) {
    int wid = (blockIdx.x * blockDim.x + threadIdx.x) >> 5;
    int lane = threadIdx.x & 31;
    int stride = (gridDim.x * blockDim.x) >> 5;
    int cnt = g_doubt_cnt;
    for (int i = wid; i < cnt; i += stride) {
        int4 dq = g_doubt[i];
        int n = dq.x, c1 = dq.y, c2 = dq.z;
        int bb = n >> 10, hw = n & 1023;
        const float* zp = z + bb * (D * HW) + hw;
        const float* p1 = cb + c1 * D;
        const float* p2 = cb + c2 * D;
        float zz = 0.f, d1 = 0.f, d2 = 0.f;
#pragma unroll
        for (int d = lane; d < D; d += 32) {
            float ze = zp[d * HW];
            zz = fmaf(ze, ze, zz);
            d1 = fmaf(ze, p1[d], d1);
            d2 = fmaf(ze, p2[d], d2);
        }
#pragma unroll
        for (int o = 16; o; o >>= 1) {
            zz += __shfl_xor_sync(~0u, zz, o);
            d1 += __shfl_xor_sync(~0u, d1, o);
            d2 += __shfl_xor_sync(~0u, d2, o);
        }
        if (lane == 0) {
            float D1 = __fadd_rn(__fsub_rn(zz, __fmul_rn(2.f, d1)), g_cnorm[c1]);
            float D2 = __fadd_rn(__fsub_rn(zz, __fmul_rn(2.f, d2)), g_cnorm[c2]);
            int win = (D2 < D1 || (D2 == D1 && c2 < c1)) ? c2 : c1;
            g_idx[n] = win;
        }
    }
}

// ---------------- Kernel 4: outputs ----------------
__global__ __launch_bounds__(256) void vq_out(const float* __restrict__ z,
                                              const float* __restrict__ cb,
                                              float* __restrict__ out) {
    __shared__ int rowIdx[128];
    __shared__ float wsum[8];
    const int t = threadIdx.x;
    const int n0 = blockIdx.x * 128;
    const int b = n0 >> 10, hw0 = n0 & 1023;
    if (t < 128) {
        int idx = g_idx[n0 + t];
        rowIdx[t] = idx;
        out[IDX_OFF + n0 + t] = (float)idx;
    }
    __syncthreads();
    const float* zb = z + b * (D * HW) + hw0;
    float* outz = out + b * (D * HW) + hw0;
    float lsum = 0.f;
#pragma unroll 4
    for (int j = 0; j < 128; j++) {
        int l = j * 256 + t;
        int i = l & 127, d = l >> 7;
        float ze = zb[d * HW + i];
        float zq = __ldg(cb + rowIdx[i] * D + d);
        float diff = zq - ze;
        outz[d * HW + i] = ze + diff;
        lsum = fmaf(diff, diff, lsum);
    }
#pragma unroll
    for (int o = 16; o; o >>= 1) lsum += __shfl_xor_sync(~0u, lsum, o);
    if ((t & 31) == 0) wsum[t >> 5] = lsum;
    __syncthreads();
    if (t == 0) {
        float s = 0.f;
#pragma unroll
        for (int ww = 0; ww < 8; ww++) s += wsum[ww];
        g_partial[blockIdx.x] = s;
    }
}

__global__ void finalize_kernel(float* __restrict__ out) {
    float s = 0.f;
    for (int i = 0; i < NBLK; i++) s += g_partial[i];
    float mean = s / 8388608.f;
    out[LOSS_OFF] = mean + 0.25f * mean;
}

// ---------------------------------------------------------------------------
extern "C" void kernel_launch(void* const* d_in, const int* in_sizes, int n_in,
                              void* d_out, int out_size) {
    const float* z  = (const float*)d_in[0];
    const float* cb = (const float*)d_in[1];
    float* out = (float*)d_out;

    cudaFuncSetAttribute(vq_gemm, cudaFuncAttributeMaxDynamicSharedMemorySize, SMEM_SZ);

    prep_kernel<<<1024, 256>>>(cb);
    cnorm_kernel<<<128, 256>>>(cb);
    vq_gemm<<<NBLK_G, 256, SMEM_SZ>>>(z);
    rescue_kernel<<<32, 256>>>(z, cb);
    vq_out<<<NBLK, 256>>>(z, cb, out);
    finalize_kernel<<<1, 1>>>(out);
}

// round 6
// speedup vs baseline: 1.1706x; 1.1706x over previous
#include <cuda_runtime.h>
#include <cuda_bf16.h>
#include <cstdint>

#define D        256
#define K        1024
#define HW       1024
#define NTOK     32768
#define NBLK     256
#define IDX_OFF  8388608
#define LOSS_OFF 8421376
#define MARGIN   0.05f

// gemm smem layout (bytes). 128 tokens/block, chunks of 32 codes.
#define OFF_AH   0          // 128 x 264 halves = 67584
#define OFF_AL   67584
#define OFF_B    135168     // 2 bufs x 33792 (2 halves x 32 codes x 528B)
#define BBUF_SZ  33792
#define BHALF_SZ 16896
#define OFF_CN   202752
#define OFF_STG  206848
#define SMEM_SZ  210944

__device__ float    g_cnorm[K];
__device__ float    g_partial[NBLK];
__device__ int      g_idx[NTOK];
__device__ int4     g_doubt[NTOK];
__device__ int      g_doubt_cnt;
__device__ uint16_t g_cbh[K * D];
__device__ uint16_t g_cbl[K * D];

// ---------------- helpers ----------------
__device__ __forceinline__ uint32_t smem_u32(const void* p) {
    uint32_t a;
    asm("{ .reg .u64 t; cvta.to.shared.u64 t, %1; cvt.u32.u64 %0, t; }" : "=r"(a) : "l"(p));
    return a;
}
#define CP_ASYNC16(dst, src) \
    asm volatile("cp.async.cg.shared.global [%0], [%1], 16;" :: "r"(dst), "l"(src) : "memory")
#define CP_COMMIT() asm volatile("cp.async.commit_group;" ::: "memory")
#define CP_WAIT1()  asm volatile("cp.async.wait_group 1;" ::: "memory")
#define CP_WAIT0()  asm volatile("cp.async.wait_group 0;" ::: "memory")

__device__ __forceinline__ void ldsm_x4(uint32_t* r, uint32_t a) {
    asm volatile("ldmatrix.sync.aligned.m8n8.x4.shared.b16 {%0,%1,%2,%3}, [%4];"
        : "=r"(r[0]), "=r"(r[1]), "=r"(r[2]), "=r"(r[3]) : "r"(a));
}
__device__ __forceinline__ void mma_bf16(float* c, const uint32_t* a, const uint32_t* b) {
    asm volatile(
        "mma.sync.aligned.m16n8k16.row.col.f32.bf16.bf16.f32 "
        "{%0,%1,%2,%3}, {%4,%5,%6,%7}, {%8,%9}, {%0,%1,%2,%3};"
        : "+f"(c[0]), "+f"(c[1]), "+f"(c[2]), "+f"(c[3])
        : "r"(a[0]), "r"(a[1]), "r"(a[2]), "r"(a[3]), "r"(b[0]), "r"(b[1]));
}
__device__ __forceinline__ bool better(float v, int i, float V, int I) {
    return v < V || (v == V && i < I);
}

// ---------------- Kernel 0: split codebook to bf16 hi/lo ----------------
__global__ void prep_kernel(const float* __restrict__ cb) {
    int i = blockIdx.x * 256 + threadIdx.x;
    float v = cb[i];
    __nv_bfloat16 h = __float2bfloat16(v);
    g_cbh[i] = __bfloat16_as_ushort(h);
    g_cbl[i] = __bfloat16_as_ushort(__float2bfloat16(v - __bfloat162float(h)));
}

// ---------------- Kernel 1: cnorm + counter reset ----------------
__global__ void cnorm_kernel(const float* __restrict__ cb) {
    if (blockIdx.x == 0 && threadIdx.x == 0) g_doubt_cnt = 0;
    int k = blockIdx.x * 8 + (threadIdx.x >> 5);
    int lane = threadIdx.x & 31;
    const float* row = cb + k * D;
    float s = 0.f;
#pragma unroll
    for (int d = lane; d < D; d += 32) { float v = row[d]; s = fmaf(v, v, s); }
#pragma unroll
    for (int o = 16; o; o >>= 1) s += __shfl_xor_sync(~0u, s, o);
    if (lane == 0) g_cnorm[k] = s;
}

// ---------------- Kernel 2: HMMA bf16x3 GEMM + top-2 argmin ----------------
// 256 blocks x 128 tokens. Warp tile 32 tok x 16 codes; chunks of 32 codes.
__global__ __launch_bounds__(256, 1) void vq_gemm(const float* __restrict__ z) {
    extern __shared__ char sm[];
    const uint32_t su = smem_u32(sm);
    const int t = threadIdx.x, w = t >> 5, lane = t & 31;
    const int g = lane >> 2, p = lane & 3;
    const int mw = w >> 1, nw = w & 1;
    const int n0 = blockIdx.x * 128;
    const int b = n0 >> 10, hw0 = n0 & 1023;
    const float* zb = z + b * (D * HW) + hw0;

    uint16_t* sAh = (uint16_t*)(sm + OFF_AH);
    uint16_t* sAl = (uint16_t*)(sm + OFF_AL);
    float*    scn = (float*)(sm + OFF_CN);
    float4*   stg = (float4*)(sm + OFF_STG);

    // ---- A: load z coalesced (128 tokens x 256 dims), split hi/lo into smem ----
#pragma unroll
    for (int j = 0; j < 32; j++) {
        int l = j * 256 + t;
        int d = l >> 5, f4 = l & 31;
        float4 v = *(const float4*)(zb + d * HW + f4 * 4);
        float vv[4] = {v.x, v.y, v.z, v.w};
#pragma unroll
        for (int q = 0; q < 4; q++) {
            int tok = f4 * 4 + q;
            __nv_bfloat16 h = __float2bfloat16(vv[q]);
            sAh[tok * 264 + d] = __bfloat16_as_ushort(h);
            sAl[tok * 264 + d] =
                __bfloat16_as_ushort(__float2bfloat16(vv[q] - __bfloat162float(h)));
        }
    }
    for (int c = t; c < K; c += 256) scn[c] = g_cnorm[c];

    // prefetch B chunk 0 (32 codes, hi+lo): 2048 x cp16, 8 per thread
#pragma unroll
    for (int j = 0; j < 8; j++) {
        int s = j * 256 + t;
        int half = s >> 10, code = (s >> 5) & 31, seg = s & 31;
        uint32_t dst = su + OFF_B + half * BHALF_SZ + code * 528 + seg * 16;
        const char* src = (const char*)(half ? g_cbl : g_cbh) + code * 512 + seg * 16;
        CP_ASYNC16(dst, src);
    }
    CP_COMMIT();
    __syncthreads();

    // ldmatrix lane addresses
    const int l8 = lane & 7, mat = lane >> 3;
    const uint32_t aoff = (uint32_t)((mw * 32 + l8 + (mat & 1) * 8) * 528 + (mat >> 1) * 16);
    const uint32_t aAddrH = su + OFF_AH + aoff;
    const uint32_t aAddrL = su + OFF_AL + aoff;
    // B x4: mat 0..3 -> (n-group mat>>1, k-half mat&1)
    const uint32_t boff = (uint32_t)((nw * 16 + (mat >> 1) * 8 + l8) * 528 + (mat & 1) * 16);

    float rv1[2][2], rv2[2][2];
    int   ri1[2][2], ri2[2][2];
#pragma unroll
    for (int mt = 0; mt < 2; mt++)
#pragma unroll
        for (int rr = 0; rr < 2; rr++) {
            rv1[mt][rr] = 3.4e38f; rv2[mt][rr] = 3.4e38f;
            ri1[mt][rr] = 0; ri2[mt][rr] = 0;
        }

    for (int nc = 0; nc < 32; nc++) {
        if (nc < 31) {
            int nn = nc + 1, buf = nn & 1;
#pragma unroll
            for (int j = 0; j < 8; j++) {
                int s = j * 256 + t;
                int half = s >> 10, code = (s >> 5) & 31, seg = s & 31;
                uint32_t dst = su + OFF_B + buf * BBUF_SZ + half * BHALF_SZ + code * 528 + seg * 16;
                const char* src = (const char*)(half ? g_cbl : g_cbh)
                                + (nn * 32 + code) * 512 + seg * 16;
                CP_ASYNC16(dst, src);
            }
            CP_COMMIT();
            CP_WAIT1();
        } else {
            CP_WAIT0();
        }
        __syncthreads();

        const uint32_t base = su + OFF_B + (uint32_t)(nc & 1) * BBUF_SZ;
        const uint32_t bAddrH = base + boff;
        const uint32_t bAddrL = base + BHALF_SZ + boff;

        float acc0[2][2][4], acc1[2][2][4], acc2[2][2][4];
#pragma unroll
        for (int mt = 0; mt < 2; mt++)
#pragma unroll
            for (int nt = 0; nt < 2; nt++)
#pragma unroll
                for (int q = 0; q < 4; q++) {
                    acc0[mt][nt][q] = 0.f; acc1[mt][nt][q] = 0.f; acc2[mt][nt][q] = 0.f;
                }

        // fragment double-buffer across ks
        uint32_t ah[2][2][4], al[2][2][4], bh[2][4], bl[2][4];
#pragma unroll
        for (int mt = 0; mt < 2; mt++) {
            ldsm_x4(ah[0][mt], aAddrH + mt * (16 * 528));
            ldsm_x4(al[0][mt], aAddrL + mt * (16 * 528));
        }
        ldsm_x4(bh[0], bAddrH);
        ldsm_x4(bl[0], bAddrL);

#pragma unroll
        for (int ks = 0; ks < 16; ks++) {
            const int cur = ks & 1, nxt = cur ^ 1;
            if (ks < 15) {
                uint32_t ko = (uint32_t)((ks + 1) * 32);
#pragma unroll
                for (int mt = 0; mt < 2; mt++) {
                    ldsm_x4(ah[nxt][mt], aAddrH + mt * (16 * 528) + ko);
                    ldsm_x4(al[nxt][mt], aAddrL + mt * (16 * 528) + ko);
                }
                ldsm_x4(bh[nxt], bAddrH + ko);
                ldsm_x4(bl[nxt], bAddrL + ko);
            }
#pragma unroll
            for (int mt = 0; mt < 2; mt++)
#pragma unroll
                for (int nt = 0; nt < 2; nt++) {
                    mma_bf16(acc0[mt][nt], ah[cur][mt], &bh[cur][nt * 2]);
                    mma_bf16(acc1[mt][nt], ah[cur][mt], &bl[cur][nt * 2]);
                    mma_bf16(acc2[mt][nt], al[cur][mt], &bh[cur][nt * 2]);
                }
        }

        // fold into running top-2 (codes ascending per thread)
#pragma unroll
        for (int nt = 0; nt < 2; nt++)
#pragma unroll
            for (int q = 0; q < 2; q++) {
                int c = nc * 32 + nw * 16 + nt * 8 + 2 * p + q;
                float cn = scn[c];
#pragma unroll
                for (int mt = 0; mt < 2; mt++)
#pragma unroll
                    for (int rr = 0; rr < 2; rr++) {
                        float dot = acc0[mt][nt][rr * 2 + q] + acc1[mt][nt][rr * 2 + q]
                                  + acc2[mt][nt][rr * 2 + q];
                        float v = fmaf(-2.f, dot, cn);
                        if (v < rv1[mt][rr]) {
                            rv2[mt][rr] = rv1[mt][rr]; ri2[mt][rr] = ri1[mt][rr];
                            rv1[mt][rr] = v;           ri1[mt][rr] = c;
                        } else if (v < rv2[mt][rr]) {
                            rv2[mt][rr] = v;           ri2[mt][rr] = c;
                        }
                    }
            }
        __syncthreads();
    }

    // ---- merge top-2 across p lanes (xor 1, 2) ----
#pragma unroll
    for (int o = 1; o <= 2; o <<= 1) {
#pragma unroll
        for (int mt = 0; mt < 2; mt++)
#pragma unroll
            for (int rr = 0; rr < 2; rr++) {
                float ov1 = __shfl_xor_sync(~0u, rv1[mt][rr], o);
                int   oi1 = __shfl_xor_sync(~0u, ri1[mt][rr], o);
                float ov2 = __shfl_xor_sync(~0u, rv2[mt][rr], o);
                int   oi2 = __shfl_xor_sync(~0u, ri2[mt][rr], o);
                if (better(ov1, oi1, rv1[mt][rr], ri1[mt][rr])) {
                    if (better(rv1[mt][rr], ri1[mt][rr], ov2, oi2)) {
                        rv2[mt][rr] = rv1[mt][rr]; ri2[mt][rr] = ri1[mt][rr];
                    } else { rv2[mt][rr] = ov2; ri2[mt][rr] = oi2; }
                    rv1[mt][rr] = ov1; ri1[mt][rr] = oi1;
                } else if (better(ov1, oi1, rv2[mt][rr], ri2[mt][rr])) {
                    rv2[mt][rr] = ov1; ri2[mt][rr] = oi1;
                }
            }
    }
    if (p == 0) {
#pragma unroll
        for (int mt = 0; mt < 2; mt++)
#pragma unroll
            for (int rr = 0; rr < 2; rr++) {
                int tok = mw * 32 + mt * 16 + rr * 8 + g;
                stg[tok * 2 + nw] = make_float4(rv1[mt][rr], __int_as_float(ri1[mt][rr]),
                                                rv2[mt][rr], __int_as_float(ri2[mt][rr]));
            }
    }
    __syncthreads();

    if (t < 128) {
        float4 a = stg[t * 2], bq = stg[t * 2 + 1];
        float v1 = a.x, v2 = a.z; int i1 = __float_as_int(a.y), i2 = __float_as_int(a.w);
        float w1 = bq.x, w2 = bq.z; int j1 = __float_as_int(bq.y), j2 = __float_as_int(bq.w);
        float fv1, fv2; int fi1, fi2;
        if (better(w1, j1, v1, i1)) {
            fv1 = w1; fi1 = j1;
            if (better(v1, i1, w2, j2)) { fv2 = v1; fi2 = i1; } else { fv2 = w2; fi2 = j2; }
        } else {
            fv1 = v1; fi1 = i1;
            if (better(w1, j1, v2, i2)) { fv2 = w1; fi2 = j1; } else { fv2 = v2; fi2 = i2; }
        }
        g_idx[n0 + t] = fi1;
        if (fv2 - fv1 < MARGIN) {
            int s = atomicAdd(&g_doubt_cnt, 1);
            g_doubt[s] = make_int4(n0 + t, fi1, fi2, 0);
        }
    }
}

// ---------------- Kernel 3: exact fp32 rescue ----------------
__global__ void rescue_kernel(const float* __restrict__ z, const float* __restrict__ cb) {
    int wid = (blockIdx.x * blockDim.x + threadIdx.x) >> 5;
    int lane = threadIdx.x & 31;
    int stride = (gridDim.x * blockDim.x) >> 5;
    int cnt = g_doubt_cnt;
    for (int i = wid; i < cnt; i += stride) {
        int4 dq = g_doubt[i];
        int n = dq.x, c1 = dq.y, c2 = dq.z;
        int bb = n >> 10, hw = n & 1023;
        const float* zp = z + bb * (D * HW) + hw;
        const float* p1 = cb + c1 * D;
        const float* p2 = cb + c2 * D;
        float zz = 0.f, d1 = 0.f, d2 = 0.f;
#pragma unroll
        for (int d = lane; d < D; d += 32) {
            float ze = zp[d * HW];
            zz = fmaf(ze, ze, zz);
            d1 = fmaf(ze, p1[d], d1);
            d2 = fmaf(ze, p2[d], d2);
        }
#pragma unroll
        for (int o = 16; o; o >>= 1) {
            zz += __shfl_xor_sync(~0u, zz, o);
            d1 += __shfl_xor_sync(~0u, d1, o);
            d2 += __shfl_xor_sync(~0u, d2, o);
        }
        if (lane == 0) {
            float D1 = __fadd_rn(__fsub_rn(zz, __fmul_rn(2.f, d1)), g_cnorm[c1]);
            float D2 = __fadd_rn(__fsub_rn(zz, __fmul_rn(2.f, d2)), g_cnorm[c2]);
            int win = (D2 < D1 || (D2 == D1 && c2 < c1)) ? c2 : c1;
            g_idx[n] = win;
        }
    }
}

// ---------------- Kernel 4: outputs ----------------
__global__ __launch_bounds__(256) void vq_out(const float* __restrict__ z,
                                              const float* __restrict__ cb,
                                              float* __restrict__ out) {
    __shared__ int rowIdx[128];
    __shared__ float wsum[8];
    const int t = threadIdx.x;
    const int n0 = blockIdx.x * 128;
    const int b = n0 >> 10, hw0 = n0 & 1023;
    if (t < 128) {
        int idx = g_idx[n0 + t];
        rowIdx[t] = idx;
        out[IDX_OFF + n0 + t] = (float)idx;
    }
    __syncthreads();
    const float* zb = z + b * (D * HW) + hw0;
    float* outz = out + b * (D * HW) + hw0;
    float lsum = 0.f;
#pragma unroll 4
    for (int j = 0; j < 128; j++) {
        int l = j * 256 + t;
        int i = l & 127, d = l >> 7;
        float ze = zb[d * HW + i];
        float zq = __ldg(cb + rowIdx[i] * D + d);
        float diff = zq - ze;
        outz[d * HW + i] = ze + diff;
        lsum = fmaf(diff, diff, lsum);
    }
#pragma unroll
    for (int o = 16; o; o >>= 1) lsum += __shfl_xor_sync(~0u, lsum, o);
    if ((t & 31) == 0) wsum[t >> 5] = lsum;
    __syncthreads();
    if (t == 0) {
        float s = 0.f;
#pragma unroll
        for (int ww = 0; ww < 8; ww++) s += wsum[ww];
        g_partial[blockIdx.x] = s;
    }
}

__global__ void finalize_kernel(float* __restrict__ out) {
    float s = 0.f;
    for (int i = 0; i < NBLK; i++) s += g_partial[i];
    float mean = s / 8388608.f;
    out[LOSS_OFF] = mean + 0.25f * mean;
}

// ---------------------------------------------------------------------------
extern "C" void kernel_launch(void* const* d_in, const int* in_sizes, int n_in,
                              void* d_out, int out_size) {
    const float* z  = (const float*)d_in[0];
    const float* cb = (const float*)d_in[1];
    float* out = (float*)d_out;

    cudaFuncSetAttribute(vq_gemm, cudaFuncAttributeMaxDynamicSharedMemorySize, SMEM_SZ);

    prep_kernel<<<1024, 256>>>(cb);
    cnorm_kernel<<<128, 256>>>(cb);
    vq_gemm<<<NBLK, 256, SMEM_SZ>>>(z);
    rescue_kernel<<<32, 256>>>(z, cb);
    vq_out<<<NBLK, 256>>>(z, cb, out);
    finalize_kernel<<<1, 1>>>(out);
}